// round 15
// baseline (speedup 1.0000x reference)
#include <cuda_runtime.h>
#include <cuda_fp16.h>
#include <stdint.h>
#include <stddef.h>
#include <math.h>

#define B_   2
#define S_   2048
#define H_   1024
#define NH_  16
#define HD_  64
#define MS_  4

// Scratch (device globals — no allocation allowed)
__device__ __half g_Xh[B_ * S_ * H_];          // x in fp16 [m][k]
__device__ __half g_WqkvT[3 * H_ * H_];        // Wqkv transposed [n][k] fp16
__device__ __half g_WoutT[H_ * H_];            // Wout transposed [n][k] fp16
__device__ __half g_Qh[B_ * NH_ * S_ * HD_];   // [b][nh][s][d], pre-scaled by 0.125*log2(e)
__device__ __half g_Kh[B_ * NH_ * S_ * HD_];
__device__ __half g_Vh[B_ * NH_ * S_ * HD_];
__device__ __half g_Oh[B_ * S_ * H_];          // [b][s][nh][d]
__device__ float  g_SW[B_ * S_ * MS_];

// ---------------------------------------------------------------------------
__device__ __forceinline__ void mma16816(float c[4], const uint32_t a[4],
                                         uint32_t b0, uint32_t b1)
{
    asm volatile(
        "mma.sync.aligned.m16n8k16.row.col.f32.f16.f16.f32 "
        "{%0,%1,%2,%3}, {%4,%5,%6,%7}, {%8,%9}, {%0,%1,%2,%3};"
        : "+f"(c[0]), "+f"(c[1]), "+f"(c[2]), "+f"(c[3])
        : "r"(a[0]), "r"(a[1]), "r"(a[2]), "r"(a[3]), "r"(b0), "r"(b1));
}

__device__ __forceinline__ void ldsm4(uint32_t r[4], uint32_t addr)
{
    asm volatile("ldmatrix.sync.aligned.m8n8.x4.shared.b16 {%0,%1,%2,%3}, [%4];"
                 : "=r"(r[0]), "=r"(r[1]), "=r"(r[2]), "=r"(r[3]) : "r"(addr));
}

__device__ __forceinline__ void ldsm4t(uint32_t r[4], uint32_t addr)
{
    asm volatile("ldmatrix.sync.aligned.m8n8.x4.trans.shared.b16 {%0,%1,%2,%3}, [%4];"
                 : "=r"(r[0]), "=r"(r[1]), "=r"(r[2]), "=r"(r[3]) : "r"(addr));
}

__device__ __forceinline__ float ex2f(float x)
{
    float y;
    asm("ex2.approx.f32 %0, %1;" : "=f"(y) : "f"(x));
    return y;
}

__device__ __forceinline__ uint32_t packh2(float x, float y)
{
    __half2 h = __floats2half2_rn(x, y);
    return *reinterpret_cast<uint32_t*>(&h);
}

__device__ __forceinline__ uint32_t smem_u32(const void* p)
{
    return (uint32_t)__cvta_generic_to_shared(p);
}

#define CP16(dst, src) asm volatile("cp.async.cg.shared.global [%0], [%1], 16;" :: "r"(dst), "l"(src))
#define CP_COMMIT()    asm volatile("cp.async.commit_group;")
#define CP_WAIT0()     asm volatile("cp.async.wait_group 0;" ::: "memory")

// Key permutation within a 128-key tile: group by divisibility class.
// dst [0,16)->k=8i (div8), [16,32)->k=8i+4 (div4), [32,64)->k=4i+2 (div2),
// [64,128)->k=2i+1 (odd)
__device__ __forceinline__ int permsrc128(int r)
{
    return r < 16 ? r * 8 : r < 32 ? (r - 16) * 8 + 4
                  : r < 64 ? (r - 32) * 4 + 2 : (r - 64) * 2 + 1;
}

// ---------------------------------------------------------------------------
// Merged prep kernel (128 threads/block):
//   blocks [0, 4096):        fuse_x (fp32->fp16 convert + scale softmax)
//   blocks [4096, 7168):     transpose+convert Wqkv (96 x 32 tiles of 32x32)
//   blocks [7168, 8192):     transpose+convert Wout (32 x 32 tiles)
// ---------------------------------------------------------------------------
__global__ __launch_bounds__(128)
void prep_kernel(const float* __restrict__ X,
                 const float* __restrict__ Wscale,
                 const float* __restrict__ bscale,
                 const float* __restrict__ Wqkv,
                 const float* __restrict__ Wout)
{
    const int bid = blockIdx.x;
    const int tid = threadIdx.x;

    if (bid < 4096) {
        const int m = bid;
        const int warp = tid >> 5, lane = tid & 31;
        const int k0 = tid * 8;

        const float4 v0 = *(const float4*)&X[(size_t)m * H_ + k0];
        const float4 v1 = *(const float4*)&X[(size_t)m * H_ + k0 + 4];

        __half2* dst = (__half2*)&g_Xh[(size_t)m * H_ + k0];
        dst[0] = __floats2half2_rn(v0.x, v0.y);
        dst[1] = __floats2half2_rn(v0.z, v0.w);
        dst[2] = __floats2half2_rn(v1.x, v1.y);
        dst[3] = __floats2half2_rn(v1.z, v1.w);

        float a[4] = {0.f, 0.f, 0.f, 0.f};
        const float xv[8] = {v0.x, v0.y, v0.z, v0.w, v1.x, v1.y, v1.z, v1.w};
#pragma unroll
        for (int j = 0; j < 8; j++) {
            const float4 w = *(const float4*)&Wscale[(size_t)(k0 + j) * 4];
            a[0] += xv[j] * w.x; a[1] += xv[j] * w.y;
            a[2] += xv[j] * w.z; a[3] += xv[j] * w.w;
        }
#pragma unroll
        for (int off = 16; off; off >>= 1) {
#pragma unroll
            for (int j = 0; j < 4; j++)
                a[j] += __shfl_xor_sync(0xffffffffu, a[j], off);
        }
        __shared__ float red[4][4];
        if (lane == 0) {
#pragma unroll
            for (int j = 0; j < 4; j++) red[warp][j] = a[j];
        }
        __syncthreads();
        if (tid == 0) {
            float v[4];
#pragma unroll
            for (int j = 0; j < 4; j++)
                v[j] = red[0][j] + red[1][j] + red[2][j] + red[3][j] + bscale[j];
            float mx = fmaxf(fmaxf(v[0], v[1]), fmaxf(v[2], v[3]));
            float e[4], sum = 0.f;
#pragma unroll
            for (int j = 0; j < 4; j++) { e[j] = __expf(v[j] - mx); sum += e[j]; }
            const float inv = 1.f / sum;
#pragma unroll
            for (int j = 0; j < 4; j++) g_SW[(size_t)m * 4 + j] = e[j] * inv;
        }
    } else {
        const float* W;
        __half* Wt;
        int N, t;
        if (bid < 4096 + 3072) {
            t = bid - 4096;
            W = Wqkv;
            N = 3 * H_;
            Wt = g_WqkvT;
        } else {
            t = bid - 7168;
            W = Wout;
            N = H_;
            Wt = g_WoutT;
        }
        const int ntiles_n = N / 32;
        const int n0 = (t % ntiles_n) * 32;
        const int k0 = (t / ntiles_n) * 32;

        __shared__ float tile[32][33];
        const int tx = tid & 31, ty = tid >> 5;
#pragma unroll
        for (int j = 0; j < 8; j++)
            tile[ty + j * 4][tx] = W[(size_t)(k0 + ty + j * 4) * N + n0 + tx];
        __syncthreads();
#pragma unroll
        for (int j = 0; j < 8; j++)
            Wt[(size_t)(n0 + ty + j * 4) * H_ + k0 + tx] =
                __float2half(tile[tx][ty + j * 4]);
    }
}

// ---------------------------------------------------------------------------
// HGEMM QKV v2: 4-warp CTA, BM=BN=128, BK=64, warp tile 32x128.
// ---------------------------------------------------------------------------
__global__ __launch_bounds__(128, 2)
void hgemm_qkv_kernel(const float* __restrict__ bias)
{
    __shared__ __half As[2][128][72];
    __shared__ __half Bs[2][128][72];

    const int bm = blockIdx.y * 128, bn = blockIdx.x * 128;
    const int tid = threadIdx.x, warp = tid >> 5, lane = tid & 31;
    const int gid = lane >> 2, th = lane & 3;
    const int lf = lane >> 3, lr8 = lane & 7;

    float acc[2][16][4];
#pragma unroll
    for (int i = 0; i < 2; i++)
#pragma unroll
        for (int j = 0; j < 16; j++)
#pragma unroll
            for (int c = 0; c < 4; c++) acc[i][j][c] = 0.f;

    auto issue = [&](int buf, int k0) {
#pragma unroll
        for (int i = 0; i < 8; i++) {
            const int idx = tid + i * 128;
            const int row = idx >> 3, c8 = (idx & 7) * 8;
            CP16(smem_u32(&As[buf][row][c8]), &g_Xh[(size_t)(bm + row) * H_ + k0 + c8]);
            CP16(smem_u32(&Bs[buf][row][c8]), &g_WqkvT[(size_t)(bn + row) * H_ + k0 + c8]);
        }
        CP_COMMIT();
    };

    issue(0, 0);
    CP_WAIT0();
    __syncthreads();

    int cur = 0;
    for (int k0 = 0; k0 < H_; k0 += 64) {
        if (k0 + 64 < H_) issue(cur ^ 1, k0 + 64);

#pragma unroll
        for (int kk = 0; kk < 64; kk += 16) {
            uint32_t af[2][4];
            ldsm4(af[0], smem_u32(&As[cur][warp * 32 + (lane & 15)][kk + (lane >> 4) * 8]));
            ldsm4(af[1], smem_u32(&As[cur][warp * 32 + 16 + (lane & 15)][kk + (lane >> 4) * 8]));
            uint32_t bfr[8][4];
#pragma unroll
            for (int j = 0; j < 8; j++)
                ldsm4(bfr[j], smem_u32(&Bs[cur][(j * 2 + (lf >> 1)) * 8 + lr8][kk + (lf & 1) * 8]));
#pragma unroll
            for (int nf = 0; nf < 16; nf++) {
                const uint32_t b0 = bfr[nf >> 1][(nf & 1) * 2];
                const uint32_t b1 = bfr[nf >> 1][(nf & 1) * 2 + 1];
                mma16816(acc[0][nf], af[0], b0, b1);
                mma16816(acc[1][nf], af[1], b0, b1);
            }
        }
        CP_WAIT0();
        __syncthreads();
        cur ^= 1;
    }

    // Scatter epilogue to Q/K/V fp16, Q pre-scaled by 0.125*log2(e)
#pragma unroll
    for (int mf = 0; mf < 2; mf++) {
#pragma unroll
        for (int nf = 0; nf < 16; nf++) {
            const int n   = bn + nf * 8 + th * 2;
            const int sel = n >> 10;
            const int rem = n & 1023;
            const int nh  = rem >> 6;
            const int d   = rem & 63;
            __half* base = (sel == 0) ? g_Qh : ((sel == 1) ? g_Kh : g_Vh);
            const float qs = (sel == 0) ? 0.125f * 1.44269504089f : 1.0f;
            const float bx = bias[n], by = bias[n + 1];
#pragma unroll
            for (int half_ = 0; half_ < 2; half_++) {
                const int m = bm + warp * 32 + mf * 16 + gid + half_ * 8;
                const int b = m >> 11, s = m & 2047;
                const float vx = (acc[mf][nf][half_ * 2 + 0] + bx) * qs;
                const float vy = (acc[mf][nf][half_ * 2 + 1] + by) * qs;
                *(__half2*)&base[(((size_t)b * NH_ + nh) * S_ + s) * HD_ + d] =
                    __floats2half2_rn(vx, vy);
            }
        }
    }
}

// ---------------------------------------------------------------------------
// Multi-scale attention v3: 4-warp CTAs (q-tile 64), 2 CTAs/SM,
// 128-key K-tiles (classes align to k16 MMA slices: no k8 MMAs),
// 2-stage cp.async double buffer, ldmatrix.trans V.
// ---------------------------------------------------------------------------
__global__ __launch_bounds__(128, 2)
void attn_ms_kernel()
{
    const int qt = blockIdx.x, h = blockIdx.y, b = blockIdx.z;
    const int tid = threadIdx.x, warp = tid >> 5, lane = tid & 31;
    const int gid = lane >> 2, th = lane & 3;
    const int lf = lane >> 3, lr8 = lane & 7;

    __shared__ __half Ks[2][128][72];   // [key(perm)][d]
    __shared__ __half Vs[2][128][72];   // [key(perm)][d]

    const size_t hb = ((size_t)b * NH_ + h) * S_ * HD_;
    const __half* Kb = g_Kh + hb;
    const __half* Vb = g_Vh + hb;
    const __half* Qb = g_Qh + hb + (size_t)qt * 64 * HD_;

    // Q fragments in registers (rows warp*16 .. +16 of the 64-row q-tile)
    uint32_t qf[4][4];
    {
        const int r0 = warp * 16 + gid;
#pragma unroll
        for (int kf = 0; kf < 4; kf++) {
            const int c = kf * 16 + th * 2;
            qf[kf][0] = *(const uint32_t*)&Qb[(size_t)r0 * 64 + c];
            qf[kf][1] = *(const uint32_t*)&Qb[(size_t)(r0 + 8) * 64 + c];
            qf[kf][2] = *(const uint32_t*)&Qb[(size_t)r0 * 64 + c + 8];
            qf[kf][3] = *(const uint32_t*)&Qb[(size_t)(r0 + 8) * 64 + c + 8];
        }
    }

    float A0[8][4], A1[8][4], A2[8][4], A3[8][4];
#pragma unroll
    for (int nf = 0; nf < 8; nf++)
#pragma unroll
        for (int c = 0; c < 4; c++) {
            A0[nf][c] = 0.f; A1[nf][c] = 0.f; A2[nf][c] = 0.f; A3[nf][c] = 0.f;
        }
    float gE[4][2] = {{0.f,0.f},{0.f,0.f},{0.f,0.f},{0.f,0.f}};

    auto issueKV = [&](int buf, int kt) {
#pragma unroll
        for (int i = 0; i < 8; i++) {
            const int slot = tid + i * 128;
            const int r = slot >> 3, c8 = (slot & 7) * 8;
            const size_t src = (size_t)(kt * 128 + permsrc128(r)) * 64 + c8;
            CP16(smem_u32(&Ks[buf][r][c8]), &Kb[src]);
            CP16(smem_u32(&Vs[buf][r][c8]), &Vb[src]);
        }
        CP_COMMIT();
    };

    issueKV(0, 0);
    CP_WAIT0();
    __syncthreads();

    int cur = 0;
    for (int kt = 0; kt < 16; kt++) {
        if (kt + 1 < 16) issueKV(cur ^ 1, kt + 1);

        // S = Q @ K^T over all 128 (permuted) keys
        float sacc[16][4];
#pragma unroll
        for (int nf = 0; nf < 16; nf++)
#pragma unroll
            for (int c = 0; c < 4; c++) sacc[nf][c] = 0.f;
#pragma unroll
        for (int kf = 0; kf < 4; kf++) {
            uint32_t bfr[8][4];
#pragma unroll
            for (int j = 0; j < 8; j++)
                ldsm4(bfr[j], smem_u32(&Ks[cur][(j * 2 + (lf >> 1)) * 8 + lr8][kf * 16 + (lf & 1) * 8]));
#pragma unroll
            for (int nf = 0; nf < 16; nf++)
                mma16816(sacc[nf], qf[kf],
                         bfr[nf >> 1][(nf & 1) * 2], bfr[nf >> 1][(nf & 1) * 2 + 1]);
        }

        // p = exp2(s); class sums. Key groups of 16 (g): g0=div8, g1=div4,
        // g2-3=div2, g4-7=odd.
        uint32_t pf[8][4];
#pragma unroll
        for (int g = 0; g < 8; g++) {
            const int cls = (g == 0) ? 3 : (g == 1) ? 2 : (g < 4) ? 1 : 0;
            const float p00 = ex2f(sacc[2 * g][0]);
            const float p01 = ex2f(sacc[2 * g][1]);
            const float p10 = ex2f(sacc[2 * g][2]);
            const float p11 = ex2f(sacc[2 * g][3]);
            const float q00 = ex2f(sacc[2 * g + 1][0]);
            const float q01 = ex2f(sacc[2 * g + 1][1]);
            const float q10 = ex2f(sacc[2 * g + 1][2]);
            const float q11 = ex2f(sacc[2 * g + 1][3]);
            gE[cls][0] += p00 + p01 + q00 + q01;
            gE[cls][1] += p10 + p11 + q10 + q11;
            pf[g][0] = packh2(p00, p01);
            pf[g][1] = packh2(p10, p11);
            pf[g][2] = packh2(q00, q01);
            pf[g][3] = packh2(q10, q11);
        }

        // AV: all k16 MMAs; key slices map 1:1 to classes.
#pragma unroll
        for (int nfd = 0; nfd < 8; nfd++) {
            uint32_t bv[16];
            ldsm4t(&bv[0],  smem_u32(&Vs[cur][lane][nfd * 8]));
            ldsm4t(&bv[4],  smem_u32(&Vs[cur][32 + lane][nfd * 8]));
            ldsm4t(&bv[8],  smem_u32(&Vs[cur][64 + lane][nfd * 8]));
            ldsm4t(&bv[12], smem_u32(&Vs[cur][96 + lane][nfd * 8]));
            mma16816(A3[nfd], pf[0], bv[0],  bv[1]);    // keys 0-15   (div8)
            mma16816(A2[nfd], pf[1], bv[2],  bv[3]);    // keys 16-31  (div4)
            mma16816(A1[nfd], pf[2], bv[4],  bv[5]);    // keys 32-47  (div2)
            mma16816(A1[nfd], pf[3], bv[6],  bv[7]);    // keys 48-63  (div2)
            mma16816(A0[nfd], pf[4], bv[8],  bv[9]);    // keys 64-79  (odd)
            mma16816(A0[nfd], pf[5], bv[10], bv[11]);   // keys 80-95  (odd)
            mma16816(A0[nfd], pf[6], bv[12], bv[13]);   // keys 96-111 (odd)
            mma16816(A0[nfd], pf[7], bv[14], bv[15]);   // keys 112-127(odd)
        }

        CP_WAIT0();
        __syncthreads();
        cur ^= 1;
    }

    // Reduce class sums across the quad
#pragma unroll
    for (int c = 0; c < 4; c++)
#pragma unroll
        for (int hh = 0; hh < 2; hh++) {
            gE[c][hh] += __shfl_xor_sync(0xffffffffu, gE[c][hh], 1);
            gE[c][hh] += __shfl_xor_sync(0xffffffffu, gE[c][hh], 2);
        }

    // Per-scale l = suffix sums; coef = w/l; class coef = prefix sums
    const int row0 = warp * 16 + gid;
    const float* swp = g_SW + ((size_t)b * S_ + qt * 64) * 4;
    float C[4][2];
#pragma unroll
    for (int hh = 0; hh < 2; hh++) {
        const float l3 = gE[3][hh];
        const float l2 = l3 + gE[2][hh];
        const float l1 = l2 + gE[1][hh];
        const float l0 = l1 + gE[0][hh];
        const float* w = swp + (row0 + hh * 8) * 4;
        const float c0 = w[0] / l0;
        const float c1 = w[1] / l1;
        const float c2 = w[2] / l2;
        const float c3 = w[3] / l3;
        C[0][hh] = c0;
        C[1][hh] = c0 + c1;
        C[2][hh] = c0 + c1 + c2;
        C[3][hh] = c0 + c1 + c2 + c3;
    }

    // Combine and write O fp16 [b][s][nh][d]
    {
        const int s0 = qt * 64 + row0;
#pragma unroll
        for (int nf = 0; nf < 8; nf++) {
            const int d = nf * 8 + th * 2;
            const float o00 = A0[nf][0] * C[0][0] + A1[nf][0] * C[1][0]
                            + A2[nf][0] * C[2][0] + A3[nf][0] * C[3][0];
            const float o01 = A0[nf][1] * C[0][0] + A1[nf][1] * C[1][0]
                            + A2[nf][1] * C[2][0] + A3[nf][1] * C[3][0];
            const float o10 = A0[nf][2] * C[0][1] + A1[nf][2] * C[1][1]
                            + A2[nf][2] * C[2][1] + A3[nf][2] * C[3][1];
            const float o11 = A0[nf][3] * C[0][1] + A1[nf][3] * C[1][1]
                            + A2[nf][3] * C[2][1] + A3[nf][3] * C[3][1];
            __half* p0 = &g_Oh[((size_t)b * S_ + s0) * H_ + h * HD_ + d];
            __half* p1 = &g_Oh[((size_t)b * S_ + s0 + 8) * H_ + h * HD_ + d];
            *(__half2*)p0 = __floats2half2_rn(o00, o01);
            *(__half2*)p1 = __floats2half2_rn(o10, o11);
        }
    }
}

// ---------------------------------------------------------------------------
// HGEMM out v2: 4-warp CTA, BM=64, BN=128, BK=64, warp tile 16x128.
// ---------------------------------------------------------------------------
__global__ __launch_bounds__(128, 3)
void hgemm_out_kernel(const float* __restrict__ bias, float* __restrict__ Y)
{
    __shared__ __half As[2][64][72];
    __shared__ __half Bs[2][128][72];

    const int bm = blockIdx.y * 64, bn = blockIdx.x * 128;
    const int tid = threadIdx.x, warp = tid >> 5, lane = tid & 31;
    const int gid = lane >> 2, th = lane & 3;
    const int lf = lane >> 3, lr8 = lane & 7;

    float acc[16][4];
#pragma unroll
    for (int j = 0; j < 16; j++)
#pragma unroll
        for (int c = 0; c < 4; c++) acc[j][c] = 0.f;

    auto issue = [&](int buf, int k0) {
#pragma unroll
        for (int i = 0; i < 4; i++) {
            const int idx = tid + i * 128;
            const int row = idx >> 3, c8 = (idx & 7) * 8;
            CP16(smem_u32(&As[buf][row][c8]), &g_Oh[(size_t)(bm + row) * H_ + k0 + c8]);
        }
#pragma unroll
        for (int i = 0; i < 8; i++) {
            const int idx = tid + i * 128;
            const int row = idx >> 3, c8 = (idx & 7) * 8;
            CP16(smem_u32(&Bs[buf][row][c8]), &g_WoutT[(size_t)(bn + row) * H_ + k0 + c8]);
        }
        CP_COMMIT();
    };

    issue(0, 0);
    CP_WAIT0();
    __syncthreads();

    int cur = 0;
    for (int k0 = 0; k0 < H_; k0 += 64) {
        if (k0 + 64 < H_) issue(cur ^ 1, k0 + 64);

#pragma unroll
        for (int kk = 0; kk < 64; kk += 16) {
            uint32_t af[4];
            ldsm4(af, smem_u32(&As[cur][warp * 16 + (lane & 15)][kk + (lane >> 4) * 8]));
            uint32_t bfr[8][4];
#pragma unroll
            for (int j = 0; j < 8; j++)
                ldsm4(bfr[j], smem_u32(&Bs[cur][(j * 2 + (lf >> 1)) * 8 + lr8][kk + (lf & 1) * 8]));
#pragma unroll
            for (int nf = 0; nf < 16; nf++) {
                const uint32_t b0 = bfr[nf >> 1][(nf & 1) * 2];
                const uint32_t b1 = bfr[nf >> 1][(nf & 1) * 2 + 1];
                mma16816(acc[nf], af, b0, b1);
            }
        }
        CP_WAIT0();
        __syncthreads();
        cur ^= 1;
    }

#pragma unroll
    for (int nf = 0; nf < 16; nf++) {
        const int n = bn + nf * 8 + th * 2;
        const float bx = bias[n], by = bias[n + 1];
#pragma unroll
        for (int half_ = 0; half_ < 2; half_++) {
            const int m = bm + warp * 16 + gid + half_ * 8;
            float2 v;
            v.x = acc[nf][half_ * 2 + 0] + bx;
            v.y = acc[nf][half_ * 2 + 1] + by;
            *(float2*)&Y[(size_t)m * H_ + n] = v;
        }
    }
}

// ---------------------------------------------------------------------------
extern "C" void kernel_launch(void* const* d_in, const int* in_sizes, int n_in,
                              void* d_out, int out_size)
{
    const float* x      = (const float*)d_in[0];
    const float* Wqkv   = (const float*)d_in[1];
    const float* bqkv   = (const float*)d_in[2];
    const float* Wout   = (const float*)d_in[3];
    const float* bout   = (const float*)d_in[4];
    const float* Wscale = (const float*)d_in[5];
    const float* bscale = (const float*)d_in[6];
    float* out = (float*)d_out;

    prep_kernel<<<4096 + 3072 + 1024, 128>>>(x, Wscale, bscale, Wqkv, Wout);

    hgemm_qkv_kernel<<<dim3(3 * H_ / 128, B_ * S_ / 128), 128>>>(bqkv);

    attn_ms_kernel<<<dim3(S_ / 64, NH_, B_), 128>>>();

    hgemm_out_kernel<<<dim3(H_ / 128, B_ * S_ / 64), 128>>>(bout, out);
}

// round 16
// speedup vs baseline: 1.0014x; 1.0014x over previous
#include <cuda_runtime.h>
#include <cuda_fp16.h>
#include <stdint.h>
#include <stddef.h>
#include <math.h>

#define B_   2
#define S_   2048
#define H_   1024
#define NH_  16
#define HD_  64
#define MS_  4

// Scratch (device globals — no allocation allowed)
__device__ __half g_Xh[B_ * S_ * H_];          // x in fp16 [m][k]
__device__ __half g_WqkvT[3 * H_ * H_];        // Wqkv transposed [n][k] fp16
__device__ __half g_WoutT[H_ * H_];            // Wout transposed [n][k] fp16
__device__ __half g_Qh[B_ * NH_ * S_ * HD_];   // [b][nh][s][d], pre-scaled by 0.125*log2(e)
__device__ __half g_Kh[B_ * NH_ * S_ * HD_];
__device__ __half g_Vh[B_ * NH_ * S_ * HD_];
__device__ __half g_Oh[B_ * S_ * H_];          // [b][s][nh][d]
__device__ float  g_SW[B_ * S_ * MS_];

// ---------------------------------------------------------------------------
__device__ __forceinline__ void mma16816(float c[4], const uint32_t a[4],
                                         uint32_t b0, uint32_t b1)
{
    asm volatile(
        "mma.sync.aligned.m16n8k16.row.col.f32.f16.f16.f32 "
        "{%0,%1,%2,%3}, {%4,%5,%6,%7}, {%8,%9}, {%0,%1,%2,%3};"
        : "+f"(c[0]), "+f"(c[1]), "+f"(c[2]), "+f"(c[3])
        : "r"(a[0]), "r"(a[1]), "r"(a[2]), "r"(a[3]), "r"(b0), "r"(b1));
}

__device__ __forceinline__ void ldsm4(uint32_t r[4], uint32_t addr)
{
    asm volatile("ldmatrix.sync.aligned.m8n8.x4.shared.b16 {%0,%1,%2,%3}, [%4];"
                 : "=r"(r[0]), "=r"(r[1]), "=r"(r[2]), "=r"(r[3]) : "r"(addr));
}

__device__ __forceinline__ void ldsm4t(uint32_t r[4], uint32_t addr)
{
    asm volatile("ldmatrix.sync.aligned.m8n8.x4.trans.shared.b16 {%0,%1,%2,%3}, [%4];"
                 : "=r"(r[0]), "=r"(r[1]), "=r"(r[2]), "=r"(r[3]) : "r"(addr));
}

__device__ __forceinline__ float ex2f(float x)
{
    float y;
    asm("ex2.approx.f32 %0, %1;" : "=f"(y) : "f"(x));
    return y;
}

__device__ __forceinline__ uint32_t packh2(float x, float y)
{
    __half2 h = __floats2half2_rn(x, y);
    return *reinterpret_cast<uint32_t*>(&h);
}

__device__ __forceinline__ uint32_t smem_u32(const void* p)
{
    return (uint32_t)__cvta_generic_to_shared(p);
}

#define CP16(dst, src) asm volatile("cp.async.cg.shared.global [%0], [%1], 16;" :: "r"(dst), "l"(src))
#define CP_COMMIT()    asm volatile("cp.async.commit_group;")
#define CP_WAIT0()     asm volatile("cp.async.wait_group 0;" ::: "memory")

// Key permutation within a 128-key tile: group by divisibility class.
// dst [0,16)->k=8i (div8), [16,32)->k=8i+4 (div4), [32,64)->k=4i+2 (div2),
// [64,128)->k=2i+1 (odd)
__device__ __forceinline__ int permsrc128(int r)
{
    return r < 16 ? r * 8 : r < 32 ? (r - 16) * 8 + 4
                  : r < 64 ? (r - 32) * 4 + 2 : (r - 64) * 2 + 1;
}

// ---------------------------------------------------------------------------
// Merged prep kernel (128 threads/block):
//   blocks [0, 4096):        fuse_x (fp32->fp16 convert + scale softmax)
//   blocks [4096, 7168):     transpose+convert Wqkv
//   blocks [7168, 8192):     transpose+convert Wout
// ---------------------------------------------------------------------------
__global__ __launch_bounds__(128)
void prep_kernel(const float* __restrict__ X,
                 const float* __restrict__ Wscale,
                 const float* __restrict__ bscale,
                 const float* __restrict__ Wqkv,
                 const float* __restrict__ Wout)
{
    const int bid = blockIdx.x;
    const int tid = threadIdx.x;

    if (bid < 4096) {
        const int m = bid;
        const int warp = tid >> 5, lane = tid & 31;
        const int k0 = tid * 8;

        const float4 v0 = *(const float4*)&X[(size_t)m * H_ + k0];
        const float4 v1 = *(const float4*)&X[(size_t)m * H_ + k0 + 4];

        __half2* dst = (__half2*)&g_Xh[(size_t)m * H_ + k0];
        dst[0] = __floats2half2_rn(v0.x, v0.y);
        dst[1] = __floats2half2_rn(v0.z, v0.w);
        dst[2] = __floats2half2_rn(v1.x, v1.y);
        dst[3] = __floats2half2_rn(v1.z, v1.w);

        float a[4] = {0.f, 0.f, 0.f, 0.f};
        const float xv[8] = {v0.x, v0.y, v0.z, v0.w, v1.x, v1.y, v1.z, v1.w};
#pragma unroll
        for (int j = 0; j < 8; j++) {
            const float4 w = *(const float4*)&Wscale[(size_t)(k0 + j) * 4];
            a[0] += xv[j] * w.x; a[1] += xv[j] * w.y;
            a[2] += xv[j] * w.z; a[3] += xv[j] * w.w;
        }
#pragma unroll
        for (int off = 16; off; off >>= 1) {
#pragma unroll
            for (int j = 0; j < 4; j++)
                a[j] += __shfl_xor_sync(0xffffffffu, a[j], off);
        }
        __shared__ float red[4][4];
        if (lane == 0) {
#pragma unroll
            for (int j = 0; j < 4; j++) red[warp][j] = a[j];
        }
        __syncthreads();
        if (tid == 0) {
            float v[4];
#pragma unroll
            for (int j = 0; j < 4; j++)
                v[j] = red[0][j] + red[1][j] + red[2][j] + red[3][j] + bscale[j];
            float mx = fmaxf(fmaxf(v[0], v[1]), fmaxf(v[2], v[3]));
            float e[4], sum = 0.f;
#pragma unroll
            for (int j = 0; j < 4; j++) { e[j] = __expf(v[j] - mx); sum += e[j]; }
            const float inv = 1.f / sum;
#pragma unroll
            for (int j = 0; j < 4; j++) g_SW[(size_t)m * 4 + j] = e[j] * inv;
        }
    } else {
        const float* W;
        __half* Wt;
        int N, t;
        if (bid < 4096 + 3072) {
            t = bid - 4096;
            W = Wqkv;
            N = 3 * H_;
            Wt = g_WqkvT;
        } else {
            t = bid - 7168;
            W = Wout;
            N = H_;
            Wt = g_WoutT;
        }
        const int ntiles_n = N / 32;
        const int n0 = (t % ntiles_n) * 32;
        const int k0 = (t / ntiles_n) * 32;

        __shared__ float tile[32][33];
        const int tx = tid & 31, ty = tid >> 5;
#pragma unroll
        for (int j = 0; j < 8; j++)
            tile[ty + j * 4][tx] = W[(size_t)(k0 + ty + j * 4) * N + n0 + tx];
        __syncthreads();
#pragma unroll
        for (int j = 0; j < 8; j++)
            Wt[(size_t)(n0 + ty + j * 4) * H_ + k0 + tx] =
                __float2half(tile[tx][ty + j * 4]);
    }
}

// ---------------------------------------------------------------------------
// HGEMM QKV v2: 4-warp CTA, BM=BN=128, BK=64, warp tile 32x128.
// ---------------------------------------------------------------------------
__global__ __launch_bounds__(128, 2)
void hgemm_qkv_kernel(const float* __restrict__ bias)
{
    __shared__ __half As[2][128][72];
    __shared__ __half Bs[2][128][72];

    const int bm = blockIdx.y * 128, bn = blockIdx.x * 128;
    const int tid = threadIdx.x, warp = tid >> 5, lane = tid & 31;
    const int gid = lane >> 2, th = lane & 3;
    const int lf = lane >> 3, lr8 = lane & 7;

    float acc[2][16][4];
#pragma unroll
    for (int i = 0; i < 2; i++)
#pragma unroll
        for (int j = 0; j < 16; j++)
#pragma unroll
            for (int c = 0; c < 4; c++) acc[i][j][c] = 0.f;

    auto issue = [&](int buf, int k0) {
#pragma unroll
        for (int i = 0; i < 8; i++) {
            const int idx = tid + i * 128;
            const int row = idx >> 3, c8 = (idx & 7) * 8;
            CP16(smem_u32(&As[buf][row][c8]), &g_Xh[(size_t)(bm + row) * H_ + k0 + c8]);
            CP16(smem_u32(&Bs[buf][row][c8]), &g_WqkvT[(size_t)(bn + row) * H_ + k0 + c8]);
        }
        CP_COMMIT();
    };

    issue(0, 0);
    CP_WAIT0();
    __syncthreads();

    int cur = 0;
    for (int k0 = 0; k0 < H_; k0 += 64) {
        if (k0 + 64 < H_) issue(cur ^ 1, k0 + 64);

#pragma unroll
        for (int kk = 0; kk < 64; kk += 16) {
            uint32_t af[2][4];
            ldsm4(af[0], smem_u32(&As[cur][warp * 32 + (lane & 15)][kk + (lane >> 4) * 8]));
            ldsm4(af[1], smem_u32(&As[cur][warp * 32 + 16 + (lane & 15)][kk + (lane >> 4) * 8]));
            uint32_t bfr[8][4];
#pragma unroll
            for (int j = 0; j < 8; j++)
                ldsm4(bfr[j], smem_u32(&Bs[cur][(j * 2 + (lf >> 1)) * 8 + lr8][kk + (lf & 1) * 8]));
#pragma unroll
            for (int nf = 0; nf < 16; nf++) {
                const uint32_t b0 = bfr[nf >> 1][(nf & 1) * 2];
                const uint32_t b1 = bfr[nf >> 1][(nf & 1) * 2 + 1];
                mma16816(acc[0][nf], af[0], b0, b1);
                mma16816(acc[1][nf], af[1], b0, b1);
            }
        }
        CP_WAIT0();
        __syncthreads();
        cur ^= 1;
    }

    // Scatter epilogue to Q/K/V fp16, Q pre-scaled by 0.125*log2(e)
#pragma unroll
    for (int mf = 0; mf < 2; mf++) {
#pragma unroll
        for (int nf = 0; nf < 16; nf++) {
            const int n   = bn + nf * 8 + th * 2;
            const int sel = n >> 10;
            const int rem = n & 1023;
            const int nh  = rem >> 6;
            const int d   = rem & 63;
            __half* base = (sel == 0) ? g_Qh : ((sel == 1) ? g_Kh : g_Vh);
            const float qs = (sel == 0) ? 0.125f * 1.44269504089f : 1.0f;
            const float bx = bias[n], by = bias[n + 1];
#pragma unroll
            for (int half_ = 0; half_ < 2; half_++) {
                const int m = bm + warp * 32 + mf * 16 + gid + half_ * 8;
                const int b = m >> 11, s = m & 2047;
                const float vx = (acc[mf][nf][half_ * 2 + 0] + bx) * qs;
                const float vy = (acc[mf][nf][half_ * 2 + 1] + by) * qs;
                *(__half2*)&base[(((size_t)b * NH_ + nh) * S_ + s) * HD_ + d] =
                    __floats2half2_rn(vx, vy);
            }
        }
    }
}

// ---------------------------------------------------------------------------
// Multi-scale attention v4: 4-warp CTAs (q-tile 64), 2 CTAs/SM.
// 128-key K-tiles (16 barrier pairs, all-k16 AV) processed in two 64-key
// halves to keep the live register set at Round-14 levels (no spills).
// Half 0 = classes div8/div4/div2; half 1 = odd.
// ---------------------------------------------------------------------------
__global__ __launch_bounds__(128, 2)
void attn_ms_kernel()
{
    const int qt = blockIdx.x, h = blockIdx.y, b = blockIdx.z;
    const int tid = threadIdx.x, warp = tid >> 5, lane = tid & 31;
    const int gid = lane >> 2, th = lane & 3;
    const int lf = lane >> 3, lr8 = lane & 7;

    __shared__ __half Ks[2][128][72];   // [key(perm)][d]
    __shared__ __half Vs[2][128][72];   // [key(perm)][d]

    const size_t hb = ((size_t)b * NH_ + h) * S_ * HD_;
    const __half* Kb = g_Kh + hb;
    const __half* Vb = g_Vh + hb;
    const __half* Qb = g_Qh + hb + (size_t)qt * 64 * HD_;

    // Q fragments in registers (rows warp*16 .. +16 of the 64-row q-tile)
    uint32_t qf[4][4];
    {
        const int r0 = warp * 16 + gid;
#pragma unroll
        for (int kf = 0; kf < 4; kf++) {
            const int c = kf * 16 + th * 2;
            qf[kf][0] = *(const uint32_t*)&Qb[(size_t)r0 * 64 + c];
            qf[kf][1] = *(const uint32_t*)&Qb[(size_t)(r0 + 8) * 64 + c];
            qf[kf][2] = *(const uint32_t*)&Qb[(size_t)r0 * 64 + c + 8];
            qf[kf][3] = *(const uint32_t*)&Qb[(size_t)(r0 + 8) * 64 + c + 8];
        }
    }

    float A0[8][4], A1[8][4], A2[8][4], A3[8][4];
#pragma unroll
    for (int nf = 0; nf < 8; nf++)
#pragma unroll
        for (int c = 0; c < 4; c++) {
            A0[nf][c] = 0.f; A1[nf][c] = 0.f; A2[nf][c] = 0.f; A3[nf][c] = 0.f;
        }
    float gE[4][2] = {{0.f,0.f},{0.f,0.f},{0.f,0.f},{0.f,0.f}};

    auto issueKV = [&](int buf, int kt) {
#pragma unroll
        for (int i = 0; i < 8; i++) {
            const int slot = tid + i * 128;
            const int r = slot >> 3, c8 = (slot & 7) * 8;
            const size_t src = (size_t)(kt * 128 + permsrc128(r)) * 64 + c8;
            CP16(smem_u32(&Ks[buf][r][c8]), &Kb[src]);
            CP16(smem_u32(&Vs[buf][r][c8]), &Vb[src]);
        }
        CP_COMMIT();
    };

    issueKV(0, 0);
    CP_WAIT0();
    __syncthreads();

    int cur = 0;
    for (int kt = 0; kt < 16; kt++) {
        if (kt + 1 < 16) issueKV(cur ^ 1, kt + 1);

        // Process the 128-key tile in two 64-key halves (bounded live regs)
#pragma unroll
        for (int hf = 0; hf < 2; hf++) {
            const int kbase = hf * 64;

            // S = Q @ K^T for this half's 64 keys
            float sacc[8][4];
#pragma unroll
            for (int nf = 0; nf < 8; nf++)
#pragma unroll
                for (int c = 0; c < 4; c++) sacc[nf][c] = 0.f;
#pragma unroll
            for (int kf = 0; kf < 4; kf++) {
                uint32_t bfr[4][4];
#pragma unroll
                for (int j = 0; j < 4; j++)
                    ldsm4(bfr[j], smem_u32(&Ks[cur][kbase + (j * 2 + (lf >> 1)) * 8 + lr8][kf * 16 + (lf & 1) * 8]));
#pragma unroll
                for (int nf = 0; nf < 8; nf++)
                    mma16816(sacc[nf], qf[kf],
                             bfr[nf >> 1][(nf & 1) * 2], bfr[nf >> 1][(nf & 1) * 2 + 1]);
            }

            // exp + class sums. Key groups of 16 within this half:
            // hf==0: g0=div8, g1=div4, g2,g3=div2.  hf==1: all odd.
            uint32_t pf[4][4];
#pragma unroll
            for (int g = 0; g < 4; g++) {
                const int cls = hf ? 0 : (g == 0 ? 3 : g == 1 ? 2 : 1);
                const float p00 = ex2f(sacc[2 * g][0]);
                const float p01 = ex2f(sacc[2 * g][1]);
                const float p10 = ex2f(sacc[2 * g][2]);
                const float p11 = ex2f(sacc[2 * g][3]);
                const float q00 = ex2f(sacc[2 * g + 1][0]);
                const float q01 = ex2f(sacc[2 * g + 1][1]);
                const float q10 = ex2f(sacc[2 * g + 1][2]);
                const float q11 = ex2f(sacc[2 * g + 1][3]);
                gE[cls][0] += p00 + p01 + q00 + q01;
                gE[cls][1] += p10 + p11 + q10 + q11;
                pf[g][0] = packh2(p00, p01);
                pf[g][1] = packh2(p10, p11);
                pf[g][2] = packh2(q00, q01);
                pf[g][3] = packh2(q10, q11);
            }

            // AV: 4 k16 MMAs per d-column group
#pragma unroll
            for (int nfd = 0; nfd < 8; nfd++) {
                uint32_t bv[8];
                ldsm4t(&bv[0], smem_u32(&Vs[cur][kbase + lane][nfd * 8]));
                ldsm4t(&bv[4], smem_u32(&Vs[cur][kbase + 32 + lane][nfd * 8]));
                if (hf == 0) {
                    mma16816(A3[nfd], pf[0], bv[0], bv[1]);   // div8
                    mma16816(A2[nfd], pf[1], bv[2], bv[3]);   // div4
                    mma16816(A1[nfd], pf[2], bv[4], bv[5]);   // div2
                    mma16816(A1[nfd], pf[3], bv[6], bv[7]);   // div2
                } else {
                    mma16816(A0[nfd], pf[0], bv[0], bv[1]);   // odd
                    mma16816(A0[nfd], pf[1], bv[2], bv[3]);
                    mma16816(A0[nfd], pf[2], bv[4], bv[5]);
                    mma16816(A0[nfd], pf[3], bv[6], bv[7]);
                }
            }
        }

        CP_WAIT0();
        __syncthreads();
        cur ^= 1;
    }

    // Reduce class sums across the quad
#pragma unroll
    for (int c = 0; c < 4; c++)
#pragma unroll
        for (int hh = 0; hh < 2; hh++) {
            gE[c][hh] += __shfl_xor_sync(0xffffffffu, gE[c][hh], 1);
            gE[c][hh] += __shfl_xor_sync(0xffffffffu, gE[c][hh], 2);
        }

    // Per-scale l = suffix sums; coef = w/l; class coef = prefix sums
    const int row0 = warp * 16 + gid;
    const float* swp = g_SW + ((size_t)b * S_ + qt * 64) * 4;
    float C[4][2];
#pragma unroll
    for (int hh = 0; hh < 2; hh++) {
        const float l3 = gE[3][hh];
        const float l2 = l3 + gE[2][hh];
        const float l1 = l2 + gE[1][hh];
        const float l0 = l1 + gE[0][hh];
        const float* w = swp + (row0 + hh * 8) * 4;
        const float c0 = w[0] / l0;
        const float c1 = w[1] / l1;
        const float c2 = w[2] / l2;
        const float c3 = w[3] / l3;
        C[0][hh] = c0;
        C[1][hh] = c0 + c1;
        C[2][hh] = c0 + c1 + c2;
        C[3][hh] = c0 + c1 + c2 + c3;
    }

    // Combine and write O fp16 [b][s][nh][d]
    {
        const int s0 = qt * 64 + row0;
#pragma unroll
        for (int nf = 0; nf < 8; nf++) {
            const int d = nf * 8 + th * 2;
            const float o00 = A0[nf][0] * C[0][0] + A1[nf][0] * C[1][0]
                            + A2[nf][0] * C[2][0] + A3[nf][0] * C[3][0];
            const float o01 = A0[nf][1] * C[0][0] + A1[nf][1] * C[1][0]
                            + A2[nf][1] * C[2][0] + A3[nf][1] * C[3][0];
            const float o10 = A0[nf][2] * C[0][1] + A1[nf][2] * C[1][1]
                            + A2[nf][2] * C[2][1] + A3[nf][2] * C[3][1];
            const float o11 = A0[nf][3] * C[0][1] + A1[nf][3] * C[1][1]
                            + A2[nf][3] * C[2][1] + A3[nf][3] * C[3][1];
            __half* p0 = &g_Oh[((size_t)b * S_ + s0) * H_ + h * HD_ + d];
            __half* p1 = &g_Oh[((size_t)b * S_ + s0 + 8) * H_ + h * HD_ + d];
            *(__half2*)p0 = __floats2half2_rn(o00, o01);
            *(__half2*)p1 = __floats2half2_rn(o10, o11);
        }
    }
}

// ---------------------------------------------------------------------------
// HGEMM out v2: 4-warp CTA, BM=64, BN=128, BK=64, warp tile 16x128.
// ---------------------------------------------------------------------------
__global__ __launch_bounds__(128, 3)
void hgemm_out_kernel(const float* __restrict__ bias, float* __restrict__ Y)
{
    __shared__ __half As[2][64][72];
    __shared__ __half Bs[2][128][72];

    const int bm = blockIdx.y * 64, bn = blockIdx.x * 128;
    const int tid = threadIdx.x, warp = tid >> 5, lane = tid & 31;
    const int gid = lane >> 2, th = lane & 3;
    const int lf = lane >> 3, lr8 = lane & 7;

    float acc[16][4];
#pragma unroll
    for (int j = 0; j < 16; j++)
#pragma unroll
        for (int c = 0; c < 4; c++) acc[j][c] = 0.f;

    auto issue = [&](int buf, int k0) {
#pragma unroll
        for (int i = 0; i < 4; i++) {
            const int idx = tid + i * 128;
            const int row = idx >> 3, c8 = (idx & 7) * 8;
            CP16(smem_u32(&As[buf][row][c8]), &g_Oh[(size_t)(bm + row) * H_ + k0 + c8]);
        }
#pragma unroll
        for (int i = 0; i < 8; i++) {
            const int idx = tid + i * 128;
            const int row = idx >> 3, c8 = (idx & 7) * 8;
            CP16(smem_u32(&Bs[buf][row][c8]), &g_WoutT[(size_t)(bn + row) * H_ + k0 + c8]);
        }
        CP_COMMIT();
    };

    issue(0, 0);
    CP_WAIT0();
    __syncthreads();

    int cur = 0;
    for (int k0 = 0; k0 < H_; k0 += 64) {
        if (k0 + 64 < H_) issue(cur ^ 1, k0 + 64);

#pragma unroll
        for (int kk = 0; kk < 64; kk += 16) {
            uint32_t af[4];
            ldsm4(af, smem_u32(&As[cur][warp * 16 + (lane & 15)][kk + (lane >> 4) * 8]));
            uint32_t bfr[8][4];
#pragma unroll
            for (int j = 0; j < 8; j++)
                ldsm4(bfr[j], smem_u32(&Bs[cur][(j * 2 + (lf >> 1)) * 8 + lr8][kk + (lf & 1) * 8]));
#pragma unroll
            for (int nf = 0; nf < 16; nf++) {
                const uint32_t b0 = bfr[nf >> 1][(nf & 1) * 2];
                const uint32_t b1 = bfr[nf >> 1][(nf & 1) * 2 + 1];
                mma16816(acc[nf], af, b0, b1);
            }
        }
        CP_WAIT0();
        __syncthreads();
        cur ^= 1;
    }

#pragma unroll
    for (int nf = 0; nf < 16; nf++) {
        const int n = bn + nf * 8 + th * 2;
        const float bx = bias[n], by = bias[n + 1];
#pragma unroll
        for (int half_ = 0; half_ < 2; half_++) {
            const int m = bm + warp * 16 + gid + half_ * 8;
            float2 v;
            v.x = acc[nf][half_ * 2 + 0] + bx;
            v.y = acc[nf][half_ * 2 + 1] + by;
            *(float2*)&Y[(size_t)m * H_ + n] = v;
        }
    }
}

// ---------------------------------------------------------------------------
extern "C" void kernel_launch(void* const* d_in, const int* in_sizes, int n_in,
                              void* d_out, int out_size)
{
    const float* x      = (const float*)d_in[0];
    const float* Wqkv   = (const float*)d_in[1];
    const float* bqkv   = (const float*)d_in[2];
    const float* Wout   = (const float*)d_in[3];
    const float* bout   = (const float*)d_in[4];
    const float* Wscale = (const float*)d_in[5];
    const float* bscale = (const float*)d_in[6];
    float* out = (float*)d_out;

    prep_kernel<<<4096 + 3072 + 1024, 128>>>(x, Wscale, bscale, Wqkv, Wout);

    hgemm_qkv_kernel<<<dim3(3 * H_ / 128, B_ * S_ / 128), 128>>>(bqkv);

    attn_ms_kernel<<<dim3(S_ / 64, NH_, B_), 128>>>();

    hgemm_out_kernel<<<dim3(H_ / 128, B_ * S_ / 64), 128>>>(bout, out);
}

// round 17
// speedup vs baseline: 1.0495x; 1.0481x over previous
#include <cuda_runtime.h>
#include <cuda_fp16.h>
#include <stdint.h>
#include <stddef.h>
#include <math.h>

#define B_   2
#define S_   2048
#define H_   1024
#define NH_  16
#define HD_  64
#define MS_  4

// Scratch (device globals — no allocation allowed)
__device__ __half g_Xh[B_ * S_ * H_];          // x in fp16 [m][k]
__device__ __half g_WqkvT[3 * H_ * H_];        // Wqkv transposed [n][k] fp16
__device__ __half g_WoutT[H_ * H_];            // Wout transposed [n][k] fp16
__device__ __half g_Qh[B_ * NH_ * S_ * HD_];   // [b][nh][s][d], pre-scaled by 0.125*log2(e)
__device__ __half g_Kh[B_ * NH_ * S_ * HD_];
__device__ __half g_Vh[B_ * NH_ * S_ * HD_];
__device__ __half g_Oh[B_ * S_ * H_];          // [b][s][nh][d]
__device__ float  g_SW[B_ * S_ * MS_];

// ---------------------------------------------------------------------------
__device__ __forceinline__ void mma16816(float c[4], const uint32_t a[4],
                                         uint32_t b0, uint32_t b1)
{
    asm volatile(
        "mma.sync.aligned.m16n8k16.row.col.f32.f16.f16.f32 "
        "{%0,%1,%2,%3}, {%4,%5,%6,%7}, {%8,%9}, {%0,%1,%2,%3};"
        : "+f"(c[0]), "+f"(c[1]), "+f"(c[2]), "+f"(c[3])
        : "r"(a[0]), "r"(a[1]), "r"(a[2]), "r"(a[3]), "r"(b0), "r"(b1));
}

__device__ __forceinline__ void mma16808(float c[4], uint32_t a0, uint32_t a1,
                                         uint32_t b0)
{
    asm volatile(
        "mma.sync.aligned.m16n8k8.row.col.f32.f16.f16.f32 "
        "{%0,%1,%2,%3}, {%4,%5}, {%6}, {%0,%1,%2,%3};"
        : "+f"(c[0]), "+f"(c[1]), "+f"(c[2]), "+f"(c[3])
        : "r"(a0), "r"(a1), "r"(b0));
}

__device__ __forceinline__ void ldsm4(uint32_t r[4], uint32_t addr)
{
    asm volatile("ldmatrix.sync.aligned.m8n8.x4.shared.b16 {%0,%1,%2,%3}, [%4];"
                 : "=r"(r[0]), "=r"(r[1]), "=r"(r[2]), "=r"(r[3]) : "r"(addr));
}

__device__ __forceinline__ void ldsm4t(uint32_t r[4], uint32_t addr)
{
    asm volatile("ldmatrix.sync.aligned.m8n8.x4.trans.shared.b16 {%0,%1,%2,%3}, [%4];"
                 : "=r"(r[0]), "=r"(r[1]), "=r"(r[2]), "=r"(r[3]) : "r"(addr));
}

__device__ __forceinline__ float ex2f(float x)
{
    float y;
    asm("ex2.approx.f32 %0, %1;" : "=f"(y) : "f"(x));
    return y;
}

__device__ __forceinline__ uint32_t packh2(float x, float y)
{
    __half2 h = __floats2half2_rn(x, y);
    return *reinterpret_cast<uint32_t*>(&h);
}

__device__ __forceinline__ uint32_t smem_u32(const void* p)
{
    return (uint32_t)__cvta_generic_to_shared(p);
}

#define CP16(dst, src) asm volatile("cp.async.cg.shared.global [%0], [%1], 16;" :: "r"(dst), "l"(src))
#define CP_COMMIT()    asm volatile("cp.async.commit_group;")
#define CP_WAIT0()     asm volatile("cp.async.wait_group 0;" ::: "memory")
#define CP_WAIT1()     asm volatile("cp.async.wait_group 1;" ::: "memory")

// Key permutation within a 64-key tile: group by divisibility class.
// dst [0,8)->k=8i (div8), [8,16)->k=8i+4, [16,32)->k=4i+2, [32,64)->k=2i+1
__device__ __forceinline__ int permsrc(int r)
{
    return r < 8 ? r * 8 : r < 16 ? (r - 8) * 8 + 4
                 : r < 32 ? (r - 16) * 4 + 2 : (r - 32) * 2 + 1;
}

// ---------------------------------------------------------------------------
// Merged prep kernel (128 threads/block):
//   blocks [0, 4096):        fuse_x (fp32->fp16 convert + scale softmax)
//   blocks [4096, 7168):     transpose+convert Wqkv
//   blocks [7168, 8192):     transpose+convert Wout
// ---------------------------------------------------------------------------
__global__ __launch_bounds__(128)
void prep_kernel(const float* __restrict__ X,
                 const float* __restrict__ Wscale,
                 const float* __restrict__ bscale,
                 const float* __restrict__ Wqkv,
                 const float* __restrict__ Wout)
{
    const int bid = blockIdx.x;
    const int tid = threadIdx.x;

    if (bid < 4096) {
        const int m = bid;
        const int warp = tid >> 5, lane = tid & 31;
        const int k0 = tid * 8;

        const float4 v0 = *(const float4*)&X[(size_t)m * H_ + k0];
        const float4 v1 = *(const float4*)&X[(size_t)m * H_ + k0 + 4];

        __half2* dst = (__half2*)&g_Xh[(size_t)m * H_ + k0];
        dst[0] = __floats2half2_rn(v0.x, v0.y);
        dst[1] = __floats2half2_rn(v0.z, v0.w);
        dst[2] = __floats2half2_rn(v1.x, v1.y);
        dst[3] = __floats2half2_rn(v1.z, v1.w);

        float a[4] = {0.f, 0.f, 0.f, 0.f};
        const float xv[8] = {v0.x, v0.y, v0.z, v0.w, v1.x, v1.y, v1.z, v1.w};
#pragma unroll
        for (int j = 0; j < 8; j++) {
            const float4 w = *(const float4*)&Wscale[(size_t)(k0 + j) * 4];
            a[0] += xv[j] * w.x; a[1] += xv[j] * w.y;
            a[2] += xv[j] * w.z; a[3] += xv[j] * w.w;
        }
#pragma unroll
        for (int off = 16; off; off >>= 1) {
#pragma unroll
            for (int j = 0; j < 4; j++)
                a[j] += __shfl_xor_sync(0xffffffffu, a[j], off);
        }
        __shared__ float red[4][4];
        if (lane == 0) {
#pragma unroll
            for (int j = 0; j < 4; j++) red[warp][j] = a[j];
        }
        __syncthreads();
        if (tid == 0) {
            float v[4];
#pragma unroll
            for (int j = 0; j < 4; j++)
                v[j] = red[0][j] + red[1][j] + red[2][j] + red[3][j] + bscale[j];
            float mx = fmaxf(fmaxf(v[0], v[1]), fmaxf(v[2], v[3]));
            float e[4], sum = 0.f;
#pragma unroll
            for (int j = 0; j < 4; j++) { e[j] = __expf(v[j] - mx); sum += e[j]; }
            const float inv = 1.f / sum;
#pragma unroll
            for (int j = 0; j < 4; j++) g_SW[(size_t)m * 4 + j] = e[j] * inv;
        }
    } else {
        const float* W;
        __half* Wt;
        int N, t;
        if (bid < 4096 + 3072) {
            t = bid - 4096;
            W = Wqkv;
            N = 3 * H_;
            Wt = g_WqkvT;
        } else {
            t = bid - 7168;
            W = Wout;
            N = H_;
            Wt = g_WoutT;
        }
        const int ntiles_n = N / 32;
        const int n0 = (t % ntiles_n) * 32;
        const int k0 = (t / ntiles_n) * 32;

        __shared__ float tile[32][33];
        const int tx = tid & 31, ty = tid >> 5;
#pragma unroll
        for (int j = 0; j < 8; j++)
            tile[ty + j * 4][tx] = W[(size_t)(k0 + ty + j * 4) * N + n0 + tx];
        __syncthreads();
#pragma unroll
        for (int j = 0; j < 8; j++)
            Wt[(size_t)(n0 + ty + j * 4) * H_ + k0 + tx] =
                __float2half(tile[tx][ty + j * 4]);
    }
}

// ---------------------------------------------------------------------------
// HGEMM QKV v2: 4-warp CTA, BM=BN=128, BK=64, warp tile 32x128.
// ---------------------------------------------------------------------------
__global__ __launch_bounds__(128, 2)
void hgemm_qkv_kernel(const float* __restrict__ bias)
{
    __shared__ __half As[2][128][72];
    __shared__ __half Bs[2][128][72];

    const int bm = blockIdx.y * 128, bn = blockIdx.x * 128;
    const int tid = threadIdx.x, warp = tid >> 5, lane = tid & 31;
    const int gid = lane >> 2, th = lane & 3;
    const int lf = lane >> 3, lr8 = lane & 7;

    float acc[2][16][4];
#pragma unroll
    for (int i = 0; i < 2; i++)
#pragma unroll
        for (int j = 0; j < 16; j++)
#pragma unroll
            for (int c = 0; c < 4; c++) acc[i][j][c] = 0.f;

    auto issue = [&](int buf, int k0) {
#pragma unroll
        for (int i = 0; i < 8; i++) {
            const int idx = tid + i * 128;
            const int row = idx >> 3, c8 = (idx & 7) * 8;
            CP16(smem_u32(&As[buf][row][c8]), &g_Xh[(size_t)(bm + row) * H_ + k0 + c8]);
            CP16(smem_u32(&Bs[buf][row][c8]), &g_WqkvT[(size_t)(bn + row) * H_ + k0 + c8]);
        }
        CP_COMMIT();
    };

    issue(0, 0);
    CP_WAIT0();
    __syncthreads();

    int cur = 0;
    for (int k0 = 0; k0 < H_; k0 += 64) {
        if (k0 + 64 < H_) issue(cur ^ 1, k0 + 64);

#pragma unroll
        for (int kk = 0; kk < 64; kk += 16) {
            uint32_t af[2][4];
            ldsm4(af[0], smem_u32(&As[cur][warp * 32 + (lane & 15)][kk + (lane >> 4) * 8]));
            ldsm4(af[1], smem_u32(&As[cur][warp * 32 + 16 + (lane & 15)][kk + (lane >> 4) * 8]));
            uint32_t bfr[8][4];
#pragma unroll
            for (int j = 0; j < 8; j++)
                ldsm4(bfr[j], smem_u32(&Bs[cur][(j * 2 + (lf >> 1)) * 8 + lr8][kk + (lf & 1) * 8]));
#pragma unroll
            for (int nf = 0; nf < 16; nf++) {
                const uint32_t b0 = bfr[nf >> 1][(nf & 1) * 2];
                const uint32_t b1 = bfr[nf >> 1][(nf & 1) * 2 + 1];
                mma16816(acc[0][nf], af[0], b0, b1);
                mma16816(acc[1][nf], af[1], b0, b1);
            }
        }
        CP_WAIT0();
        __syncthreads();
        cur ^= 1;
    }

    // Scatter epilogue to Q/K/V fp16, Q pre-scaled by 0.125*log2(e)
#pragma unroll
    for (int mf = 0; mf < 2; mf++) {
#pragma unroll
        for (int nf = 0; nf < 16; nf++) {
            const int n   = bn + nf * 8 + th * 2;
            const int sel = n >> 10;
            const int rem = n & 1023;
            const int nh  = rem >> 6;
            const int d   = rem & 63;
            __half* base = (sel == 0) ? g_Qh : ((sel == 1) ? g_Kh : g_Vh);
            const float qs = (sel == 0) ? 0.125f * 1.44269504089f : 1.0f;
            const float bx = bias[n], by = bias[n + 1];
#pragma unroll
            for (int half_ = 0; half_ < 2; half_++) {
                const int m = bm + warp * 32 + mf * 16 + gid + half_ * 8;
                const int b = m >> 11, s = m & 2047;
                const float vx = (acc[mf][nf][half_ * 2 + 0] + bx) * qs;
                const float vy = (acc[mf][nf][half_ * 2 + 1] + by) * qs;
                *(__half2*)&base[(((size_t)b * NH_ + nh) * S_ + s) * HD_ + d] =
                    __floats2half2_rn(vx, vy);
            }
        }
    }
}

// ---------------------------------------------------------------------------
// Multi-scale attention (Round-14 best config, verbatim): 4-warp CTAs
// (q-tile 64), 2 CTAs/SM, 3-stage cp.async K/V (64-key tiles),
// ldmatrix.trans V, exact-class accumulators A3..A0.
// ---------------------------------------------------------------------------
__global__ __launch_bounds__(128, 2)
void attn_ms_kernel()
{
    const int qt = blockIdx.x, h = blockIdx.y, b = blockIdx.z;
    const int tid = threadIdx.x, warp = tid >> 5, lane = tid & 31;
    const int gid = lane >> 2, th = lane & 3;
    const int lf = lane >> 3, lr8 = lane & 7;

    __shared__ __half Ks[3][64][72];   // [key(perm)][d]
    __shared__ __half Vs[3][64][72];   // [key(perm)][d]

    const size_t hb = ((size_t)b * NH_ + h) * S_ * HD_;
    const __half* Kb = g_Kh + hb;
    const __half* Vb = g_Vh + hb;
    const __half* Qb = g_Qh + hb + (size_t)qt * 64 * HD_;

    uint32_t qf[4][4];
    {
        const int r0 = warp * 16 + gid;
#pragma unroll
        for (int kf = 0; kf < 4; kf++) {
            const int c = kf * 16 + th * 2;
            qf[kf][0] = *(const uint32_t*)&Qb[(size_t)r0 * 64 + c];
            qf[kf][1] = *(const uint32_t*)&Qb[(size_t)(r0 + 8) * 64 + c];
            qf[kf][2] = *(const uint32_t*)&Qb[(size_t)r0 * 64 + c + 8];
            qf[kf][3] = *(const uint32_t*)&Qb[(size_t)(r0 + 8) * 64 + c + 8];
        }
    }

    float A0[8][4], A1[8][4], A2[8][4], A3[8][4];
#pragma unroll
    for (int nf = 0; nf < 8; nf++)
#pragma unroll
        for (int c = 0; c < 4; c++) {
            A0[nf][c] = 0.f; A1[nf][c] = 0.f; A2[nf][c] = 0.f; A3[nf][c] = 0.f;
        }
    float gE[4][2] = {{0.f,0.f},{0.f,0.f},{0.f,0.f},{0.f,0.f}};

    auto issueKV = [&](int buf, int kt) {
#pragma unroll
        for (int i = 0; i < 4; i++) {
            const int slot = tid + i * 128;
            const int r = slot >> 3, c8 = (slot & 7) * 8;
            const size_t src = (size_t)(kt * 64 + permsrc(r)) * 64 + c8;
            CP16(smem_u32(&Ks[buf][r][c8]), &Kb[src]);
            CP16(smem_u32(&Vs[buf][r][c8]), &Vb[src]);
        }
        CP_COMMIT();
    };

    issueKV(0, 0);
    issueKV(1, 1);

    for (int kt = 0; kt < 32; kt++) {
        const int cur = kt % 3;
        CP_WAIT1();
        __syncthreads();
        if (kt + 2 < 32) issueKV((kt + 2) % 3, kt + 2);
        else CP_COMMIT();

        float sacc[8][4];
#pragma unroll
        for (int nf = 0; nf < 8; nf++)
#pragma unroll
            for (int c = 0; c < 4; c++) sacc[nf][c] = 0.f;
#pragma unroll
        for (int kf = 0; kf < 4; kf++) {
            uint32_t bfr[4][4];
#pragma unroll
            for (int j = 0; j < 4; j++)
                ldsm4(bfr[j], smem_u32(&Ks[cur][(j * 2 + (lf >> 1)) * 8 + lr8][kf * 16 + (lf & 1) * 8]));
#pragma unroll
            for (int nf = 0; nf < 8; nf++)
                mma16816(sacc[nf], qf[kf],
                         bfr[nf >> 1][(nf & 1) * 2], bfr[nf >> 1][(nf & 1) * 2 + 1]);
        }

        uint32_t pf[4][4];
#pragma unroll
        for (int kf = 0; kf < 4; kf++) {
            const float p00 = ex2f(sacc[2 * kf][0]);
            const float p01 = ex2f(sacc[2 * kf][1]);
            const float p10 = ex2f(sacc[2 * kf][2]);
            const float p11 = ex2f(sacc[2 * kf][3]);
            const float q00 = ex2f(sacc[2 * kf + 1][0]);
            const float q01 = ex2f(sacc[2 * kf + 1][1]);
            const float q10 = ex2f(sacc[2 * kf + 1][2]);
            const float q11 = ex2f(sacc[2 * kf + 1][3]);
            if (kf == 0) {
                gE[3][0] += p00 + p01; gE[3][1] += p10 + p11;   // div8
                gE[2][0] += q00 + q01; gE[2][1] += q10 + q11;   // div4
            } else if (kf == 1) {
                gE[1][0] += p00 + p01 + q00 + q01;              // div2
                gE[1][1] += p10 + p11 + q10 + q11;
            } else {
                gE[0][0] += p00 + p01 + q00 + q01;              // odd
                gE[0][1] += p10 + p11 + q10 + q11;
            }
            pf[kf][0] = packh2(p00, p01);
            pf[kf][1] = packh2(p10, p11);
            pf[kf][2] = packh2(q00, q01);
            pf[kf][3] = packh2(q10, q11);
        }

#pragma unroll
        for (int nf = 0; nf < 8; nf++) {
            uint32_t bv[8];
            ldsm4t(&bv[0], smem_u32(&Vs[cur][lane][nf * 8]));
            ldsm4t(&bv[4], smem_u32(&Vs[cur][32 + lane][nf * 8]));
            mma16808(A3[nf], pf[0][0], pf[0][1], bv[0]);
            mma16808(A2[nf], pf[0][2], pf[0][3], bv[1]);
            mma16816(A1[nf], pf[1], bv[2], bv[3]);
            mma16816(A0[nf], pf[2], bv[4], bv[5]);
            mma16816(A0[nf], pf[3], bv[6], bv[7]);
        }
    }

#pragma unroll
    for (int c = 0; c < 4; c++)
#pragma unroll
        for (int hh = 0; hh < 2; hh++) {
            gE[c][hh] += __shfl_xor_sync(0xffffffffu, gE[c][hh], 1);
            gE[c][hh] += __shfl_xor_sync(0xffffffffu, gE[c][hh], 2);
        }

    const int row0 = warp * 16 + gid;
    const float* swp = g_SW + ((size_t)b * S_ + qt * 64) * 4;
    float C[4][2];
#pragma unroll
    for (int hh = 0; hh < 2; hh++) {
        const float l3 = gE[3][hh];
        const float l2 = l3 + gE[2][hh];
        const float l1 = l2 + gE[1][hh];
        const float l0 = l1 + gE[0][hh];
        const float* w = swp + (row0 + hh * 8) * 4;
        const float c0 = w[0] / l0;
        const float c1 = w[1] / l1;
        const float c2 = w[2] / l2;
        const float c3 = w[3] / l3;
        C[0][hh] = c0;
        C[1][hh] = c0 + c1;
        C[2][hh] = c0 + c1 + c2;
        C[3][hh] = c0 + c1 + c2 + c3;
    }

    {
        const int s0 = qt * 64 + row0;
#pragma unroll
        for (int nf = 0; nf < 8; nf++) {
            const int d = nf * 8 + th * 2;
            const float o00 = A0[nf][0] * C[0][0] + A1[nf][0] * C[1][0]
                            + A2[nf][0] * C[2][0] + A3[nf][0] * C[3][0];
            const float o01 = A0[nf][1] * C[0][0] + A1[nf][1] * C[1][0]
                            + A2[nf][1] * C[2][0] + A3[nf][1] * C[3][0];
            const float o10 = A0[nf][2] * C[0][1] + A1[nf][2] * C[1][1]
                            + A2[nf][2] * C[2][1] + A3[nf][2] * C[3][1];
            const float o11 = A0[nf][3] * C[0][1] + A1[nf][3] * C[1][1]
                            + A2[nf][3] * C[2][1] + A3[nf][3] * C[3][1];
            __half* p0 = &g_Oh[((size_t)b * S_ + s0) * H_ + h * HD_ + d];
            __half* p1 = &g_Oh[((size_t)b * S_ + s0 + 8) * H_ + h * HD_ + d];
            *(__half2*)p0 = __floats2half2_rn(o00, o01);
            *(__half2*)p1 = __floats2half2_rn(o10, o11);
        }
    }
}

// ---------------------------------------------------------------------------
// HGEMM out v3: same shape as QKV v2 (4-warp CTA, BM=BN=128, BK=64,
// warp tile 32x128 — the 307 TF/s shape), fp32 output epilogue.
// ---------------------------------------------------------------------------
__global__ __launch_bounds__(128, 2)
void hgemm_out_kernel(const float* __restrict__ bias, float* __restrict__ Y)
{
    __shared__ __half As[2][128][72];
    __shared__ __half Bs[2][128][72];

    const int bm = blockIdx.y * 128, bn = blockIdx.x * 128;
    const int tid = threadIdx.x, warp = tid >> 5, lane = tid & 31;
    const int gid = lane >> 2, th = lane & 3;
    const int lf = lane >> 3, lr8 = lane & 7;

    float acc[2][16][4];
#pragma unroll
    for (int i = 0; i < 2; i++)
#pragma unroll
        for (int j = 0; j < 16; j++)
#pragma unroll
            for (int c = 0; c < 4; c++) acc[i][j][c] = 0.f;

    auto issue = [&](int buf, int k0) {
#pragma unroll
        for (int i = 0; i < 8; i++) {
            const int idx = tid + i * 128;
            const int row = idx >> 3, c8 = (idx & 7) * 8;
            CP16(smem_u32(&As[buf][row][c8]), &g_Oh[(size_t)(bm + row) * H_ + k0 + c8]);
            CP16(smem_u32(&Bs[buf][row][c8]), &g_WoutT[(size_t)(bn + row) * H_ + k0 + c8]);
        }
        CP_COMMIT();
    };

    issue(0, 0);
    CP_WAIT0();
    __syncthreads();

    int cur = 0;
    for (int k0 = 0; k0 < H_; k0 += 64) {
        if (k0 + 64 < H_) issue(cur ^ 1, k0 + 64);

#pragma unroll
        for (int kk = 0; kk < 64; kk += 16) {
            uint32_t af[2][4];
            ldsm4(af[0], smem_u32(&As[cur][warp * 32 + (lane & 15)][kk + (lane >> 4) * 8]));
            ldsm4(af[1], smem_u32(&As[cur][warp * 32 + 16 + (lane & 15)][kk + (lane >> 4) * 8]));
            uint32_t bfr[8][4];
#pragma unroll
            for (int j = 0; j < 8; j++)
                ldsm4(bfr[j], smem_u32(&Bs[cur][(j * 2 + (lf >> 1)) * 8 + lr8][kk + (lf & 1) * 8]));
#pragma unroll
            for (int nf = 0; nf < 16; nf++) {
                const uint32_t b0 = bfr[nf >> 1][(nf & 1) * 2];
                const uint32_t b1 = bfr[nf >> 1][(nf & 1) * 2 + 1];
                mma16816(acc[0][nf], af[0], b0, b1);
                mma16816(acc[1][nf], af[1], b0, b1);
            }
        }
        CP_WAIT0();
        __syncthreads();
        cur ^= 1;
    }

#pragma unroll
    for (int mf = 0; mf < 2; mf++) {
#pragma unroll
        for (int nf = 0; nf < 16; nf++) {
            const int n = bn + nf * 8 + th * 2;
            const float bx = bias[n], by = bias[n + 1];
#pragma unroll
            for (int half_ = 0; half_ < 2; half_++) {
                const int m = bm + warp * 32 + mf * 16 + gid + half_ * 8;
                float2 v;
                v.x = acc[mf][nf][half_ * 2 + 0] + bx;
                v.y = acc[mf][nf][half_ * 2 + 1] + by;
                *(float2*)&Y[(size_t)m * H_ + n] = v;
            }
        }
    }
}

// ---------------------------------------------------------------------------
extern "C" void kernel_launch(void* const* d_in, const int* in_sizes, int n_in,
                              void* d_out, int out_size)
{
    const float* x      = (const float*)d_in[0];
    const float* Wqkv   = (const float*)d_in[1];
    const float* bqkv   = (const float*)d_in[2];
    const float* Wout   = (const float*)d_in[3];
    const float* bout   = (const float*)d_in[4];
    const float* Wscale = (const float*)d_in[5];
    const float* bscale = (const float*)d_in[6];
    float* out = (float*)d_out;

    prep_kernel<<<4096 + 3072 + 1024, 128>>>(x, Wscale, bscale, Wqkv, Wout);

    hgemm_qkv_kernel<<<dim3(3 * H_ / 128, B_ * S_ / 128), 128>>>(bqkv);

    attn_ms_kernel<<<dim3(S_ / 64, NH_, B_), 128>>>();

    hgemm_out_kernel<<<dim3(H_ / 128, B_ * S_ / 128), 128>>>(bout, out);
}